// round 17
// baseline (speedup 1.0000x reference)
#include <cuda_runtime.h>
#include <math.h>
#include <stdint.h>

// Problem constants
#define NB   16      // batch
#define NPTS 512     // points per sample
#define MS   4096    // m = 64*64 grid cells
#define NIT  100     // ASGD iterations
#define NCH  16      // wd chunks per sample (32 rows per block, 4 per warp)
#define L2E  1.44269504088896f   // log2(e)

// Scratch (device globals; no allocation allowed)
__device__ float g_w[NB * MS];      // beta + 10*log(b), per sample
__device__ float g_wmax[NB];
__device__ float g_loss[NB];
__device__ float g_ot[NB];
__device__ float g_wd[NB * NCH];
__device__ unsigned int g_ctr;      // last-block counter for fused finalize

// ---------------------------------------------------------------------------
// Threefry2x32, JAX partitionable path (verified passing):
//   k2 = tf((0,1), (0,1));  idx[t] = (y0^y1 of tf(k2, (0,t))) & 511
// ---------------------------------------------------------------------------
__device__ __forceinline__ uint32_t rotl32(uint32_t x, int r) {
    return (x << r) | (x >> (32 - r));
}

__device__ __forceinline__ void tf2x32(uint32_t k0, uint32_t k1,
                                       uint32_t& x0, uint32_t& x1) {
    uint32_t ks2 = 0x1BD11BDAu ^ k0 ^ k1;
    x0 += k0; x1 += k1;
#define TF_RND(r) { x0 += x1; x1 = rotl32(x1, r); x1 ^= x0; }
    TF_RND(13) TF_RND(15) TF_RND(26) TF_RND(6)
    x0 += k1;  x1 += ks2 + 1u;
    TF_RND(17) TF_RND(29) TF_RND(16) TF_RND(24)
    x0 += ks2; x1 += k0 + 2u;
    TF_RND(13) TF_RND(15) TF_RND(26) TF_RND(6)
    x0 += k0;  x1 += k1 + 3u;
    TF_RND(17) TF_RND(29) TF_RND(16) TF_RND(24)
    x0 += k1;  x1 += ks2 + 4u;
    TF_RND(13) TF_RND(15) TF_RND(26) TF_RND(6)
    x0 += ks2; x1 += k0 + 5u;
#undef TF_RND
}

// Block reduction for 256 threads (8 warps). op: 0=sum, 1=max.
__device__ __forceinline__ float blk_red8(float v, float* sred, int op) {
    const int tid = threadIdx.x, lane = tid & 31, wid = tid >> 5;
    #pragma unroll
    for (int o = 16; o > 0; o >>= 1) {
        float t = __shfl_xor_sync(0xffffffffu, v, o);
        v = op ? fmaxf(v, t) : (v + t);
    }
    __syncthreads();
    if (lane == 0) sred[wid] = v;
    __syncthreads();
    float u = sred[lane & 7];
    #pragma unroll
    for (int o = 4; o > 0; o >>= 1) {
        float t = __shfl_xor_sync(0xffffffffu, u, o);
        u = op ? fmaxf(u, t) : (u + t);
    }
    return u;
}

// ---------------------------------------------------------------------------
// Dense scan kernel (UNCHANGED from R14 — proven 47us): one block per sample,
// 256 threads, 16 cells/thread. Warp w owns 64x8-cell slab rows [8w, 8w+8).
// Phase A: block max (no MUFU). Phase B: per-warp underflow skip (mx < gm-88
// => all contributions < 1e-38, replaced by 0; khi=0 path is 1 fma/cell).
// ---------------------------------------------------------------------------
__global__ void __launch_bounds__(256, 1)
k_scan(const float* __restrict__ normed, const float* __restrict__ unnormed,
       const float* __restrict__ pts) {
    __shared__ float2 SPT[NIT];
    __shared__ float  SCK[NIT];
    __shared__ __align__(16) float SMX[8];
    __shared__ __align__(16) float SSM[8];
    __shared__ __align__(16) float SRED[8];

    const int s    = blockIdx.x;
    const int tid  = threadIdx.x;
    const int lane = tid & 31;
    const int wid  = tid >> 5;          // 0..7

    const float2* bp2 = (const float2*)(normed + s * MS);
    const float*  up  = unnormed + s * MS;
    const float*  pp  = pts      + s * NPTS * 2;

    const int y0 = wid * 8;
    const float cx0 = (float)(16 * lane + 4);
    const float cx1 = cx0 + 8.0f;

    float2 b2[8], zb2[8], sb2[8];
    #pragma unroll
    for (int t = 0; t < 8; t++) {
        int idx = (y0 + t) * 32 + lane;
        float2 b = bp2[idx];
        b2[t] = b;
        zb2[t] = make_float2(__logf(b.x), __logf(b.y));
        sb2[t] = make_float2(0.0f, 0.0f);
    }

    if (tid < NIT) {
        uint32_t c0 = 0u, c1 = 1u;
        tf2x32(0u, 1u, c0, c1);               // k2
        uint32_t x0 = 0u, x1 = (uint32_t)(s * NIT + tid);
        tf2x32(c0, c1, x0, x1);
        int i = (int)((x0 ^ x1) & 511u);
        SPT[tid] = make_float2(pp[2 * i], pp[2 * i + 1]);
        SCK[tid] = __fdividef(512.0f, sqrtf((float)(tid + 1)));   // ck/10
    }
    __syncthreads();

    for (int k = 0; k < NIT; k++) {
        float2 p = SPT[k];
        float ck10 = SCK[k];
        float dx0 = p.x - cx0, dx1 = p.x - cx1;
        float dq0 = dx0 * dx0 * 0.1f;
        float dq1 = dx1 * dx1 * 0.1f;

        // ---- Phase A: z + block max (no MUFU) ----
        float z0[8], z1[8];
        float mx = -INFINITY;
        #pragma unroll
        for (int t = 0; t < 8; t++) {
            float dy = p.y - (float)((y0 + t) * 8 + 4);
            float dyq = dy * dy * 0.1f;
            z0[t] = zb2[t].x - dq0 - dyq;
            z1[t] = zb2[t].y - dq1 - dyq;
            mx = fmaxf(mx, fmaxf(z0[t], z1[t]));
        }
        #pragma unroll
        for (int o = 16; o > 0; o >>= 1)
            mx = fmaxf(mx, __shfl_xor_sync(0xffffffffu, mx, o));
        if (lane == 0) SMX[wid] = mx;
        __syncthreads();
        float4 ma = *(const float4*)SMX;
        float4 mb = *(const float4*)(SMX + 4);
        float gm = fmaxf(fmaxf(fmaxf(ma.x, ma.y), fmaxf(ma.z, ma.w)),
                         fmaxf(fmaxf(mb.x, mb.y), fmaxf(mb.z, mb.w)));

        // ---- Phase B: per-warp skip or exp; block sum ----
        bool active = (mx >= gm - 88.0f);
        float e0[8], e1[8];
        float se = 0.0f;
        if (active) {
            #pragma unroll
            for (int t = 0; t < 8; t++) {
                e0[t] = exp2f((z0[t] - gm) * L2E);
                e1[t] = exp2f((z1[t] - gm) * L2E);
                se += e0[t] + e1[t];
            }
        }
        #pragma unroll
        for (int o = 16; o > 0; o >>= 1)
            se += __shfl_xor_sync(0xffffffffu, se, o);
        if (lane == 0) SSM[wid] = se;
        __syncthreads();
        float4 sa = *(const float4*)SSM;
        float4 sb4 = *(const float4*)(SSM + 4);
        float bs = ((sa.x + sa.y) + (sa.z + sa.w))
                 + ((sb4.x + sb4.y) + (sb4.z + sb4.w));

        // ---- Update ----
        float a = ck10 * __fdividef(1.0f, bs);
        if (active) {
            #pragma unroll
            for (int t = 0; t < 8; t++) {
                zb2[t].x = fmaf(-a, e0[t], fmaf(ck10, b2[t].x, zb2[t].x));
                zb2[t].y = fmaf(-a, e1[t], fmaf(ck10, b2[t].y, zb2[t].y));
                sb2[t].x += zb2[t].x;
                sb2[t].y += zb2[t].y;
            }
        } else {
            #pragma unroll
            for (int t = 0; t < 8; t++) {
                zb2[t].x = fmaf(ck10, b2[t].x, zb2[t].x);
                zb2[t].y = fmaf(ck10, b2[t].y, zb2[t].y);
                sb2[t].x += zb2[t].x;
                sb2[t].y += zb2[t].y;
            }
        }
    }

    // ---- Epilogue ----
    float aveR[16], srcR[16];
    float p_ot = 0.0f, p_sc = 0.0f, p_td = 0.0f, wmx = -INFINITY;
    #pragma unroll
    for (int t = 0; t < 8; t++) {
        int jj = (y0 + t) * 64 + 2 * lane;
        float wA = 0.1f * sb2[t].x;
        float wB = 0.1f * sb2[t].y;
        float aveA = wA - 10.0f * __logf(b2[t].x);
        float aveB = wB - 10.0f * __logf(b2[t].y);
        g_w[s * MS + jj]     = wA;
        g_w[s * MS + jj + 1] = wB;
        float srcA = up[jj], srcB = up[jj + 1];
        aveR[2*t] = aveA; aveR[2*t+1] = aveB;
        srcR[2*t] = srcA; srcR[2*t+1] = srcB;
        p_ot += b2[t].x * aveA + b2[t].y * aveB;
        p_sc += srcA + srcB;
        p_td += srcA * aveA + srcB * aveB;
        wmx = fmaxf(wmx, fmaxf(wA, wB));
    }
    float ot = blk_red8(p_ot, SRED, 0);
    float sc = blk_red8(p_sc, SRED, 0);
    float td = blk_red8(p_td, SRED, 0);
    float wm = blk_red8(wmx, SRED, 1);
    float denom = sc * sc + 1e-16f;
    float q1s = sc / denom, q2s = td / denom;
    float p_ls = 0.0f;
    #pragma unroll
    for (int t = 0; t < 16; t++) p_ls += srcR[t] * (q1s * aveR[t] - q2s);
    float ls = blk_red8(p_ls, SRED, 0);
    if (tid == 0) {
        g_ot[s] = ot;
        g_loss[s] = ls;
        g_wmax[s] = wm;
        if (s == 0) g_ctr = 0;
    }
}

// ---------------------------------------------------------------------------
// wd kernel, sub-warp parallel: each warp splits into 4 groups of 8 lanes;
// each group owns one row (point). Adaptive region (verified R5/R9 math):
// stabilizer anchored at own cell with wmax guard; region M <= D10 + 350.
// Groups run concurrently in SIMT (cost = max trip count, not sum); region
// cols strided by 8 within the group -> full lane utilization.
// grid (16 chunks, 16 samples) = 256 blocks, 256 threads, 32 rows/block.
// Last block performs the deterministic finalize.
// ---------------------------------------------------------------------------
__global__ void __launch_bounds__(256)
k_wd(const float* __restrict__ pts, float* __restrict__ out) {
    const int s = blockIdx.y;
    const int chunk = blockIdx.x;
    const int tid = threadIdx.x;
    const int wid = tid >> 5, lane = tid & 31;
    const int grp = lane >> 3;          // 0..3 (row group)
    const int sl  = lane & 7;           // 0..7 (col lane within group)
    __shared__ float sw[MS];
    __shared__ float wacc[8];
    __shared__ unsigned int sflag;

    for (int j = tid; j < MS; j += 256)
        sw[j] = g_w[s * MS + j];
    const float wmax = g_wmax[s];
    __syncthreads();

    const float* pp = pts + s * NPTS * 2;

    // each group handles one row
    int i = chunk * 32 + wid * 4 + grp;
    float px = pp[2 * i], py = pp[2 * i + 1];

    int jxs = (int)(px * 0.125f);
    int jys = (int)(py * 0.125f);
    int js  = jys * 64 + jxs;
    float dxs = px - (float)(jxs * 8 + 4);
    float dys = py - (float)(jys * 8 + 4);
    float Ms  = dxs * dxs + dys * dys;
    float raws = sw[js] - Ms;              // raw units
    float D10 = wmax - raws;
    float m = raws * 0.1f + fmaxf(0.0f, D10 * 0.1f - 70.0f);
    float T = fmaxf(D10, 0.0f) + 350.0f;
    float xr = sqrtf(T);
    int jxlo = max(0,  (int)ceilf ((px - xr - 4.0f) * 0.125f));
    int jxhi = min(63, (int)floorf((px + xr - 4.0f) * 0.125f));
    int jylo = max(0,  (int)ceilf ((py - xr - 4.0f) * 0.125f));
    int jyhi = min(63, (int)floorf((py + xr - 4.0f) * 0.125f));

    float se = 0.0f, st = 0.0f;
    for (int jy = jylo; jy <= jyhi; jy++) {
        float dy = py - (float)(jy * 8 + 4);
        float yd = dy * dy;
        for (int jx = jxlo + sl; jx <= jxhi; jx += 8) {
            float dx = px - (float)(jx * 8 + 4);
            float M = yd + dx * dx;
            int j = jy * 64 + jx;
            float e = __expf((sw[j] - M) * 0.1f - m);
            se += e;
            st += e * M;
        }
    }
    // 3-stage reduce within the 8-lane group
    #pragma unroll
    for (int o = 4; o > 0; o >>= 1) {
        se += __shfl_xor_sync(0xffffffffu, se, o);
        st += __shfl_xor_sync(0xffffffffu, st, o);
    }
    se = fmaxf(se, 1e-30f);
    float acc = __fdividef(st, se);     // all 8 lanes of group hold E[M]_i

    // cross-group: lanes {l, l^8, l^16, l^24} = one lane per group
    acc += __shfl_xor_sync(0xffffffffu, acc, 8);
    acc += __shfl_xor_sync(0xffffffffu, acc, 16);

    if (lane == 0) wacc[wid] = acc;
    __syncthreads();
    if (tid == 0) {
        float t = 0.0f;
        #pragma unroll
        for (int w = 0; w < 8; w++) t += wacc[w];
        g_wd[s * NCH + chunk] = t * (1.0f / 512.0f);
        __threadfence();
        unsigned int old = atomicAdd(&g_ctr, 1u);
        sflag = (old == (NB * NCH - 1)) ? 1u : 0u;
    }
    __syncthreads();

    // ---- Fused finalize by the last block (fixed-order: deterministic) ----
    if (sflag) {
        float v = g_wd[tid];            // exactly NB*NCH = 256 partials
        #pragma unroll
        for (int o = 16; o > 0; o >>= 1)
            v += __shfl_xor_sync(0xffffffffu, v, o);
        if (lane == 0) wacc[wid] = v;
        __syncthreads();
        if (tid == 0) {
            float W = 0.0f;
            #pragma unroll
            for (int w = 0; w < 8; w++) W += wacc[w];
            float L = 0.0f, O = 0.0f;
            for (int q = 0; q < NB; q++) { L += g_loss[q]; O += g_ot[q]; }
            out[0] = L; out[1] = W; out[2] = O;
        }
    }
}

extern "C" void kernel_launch(void* const* d_in, const int* in_sizes, int n_in,
                              void* d_out, int out_size) {
    const float* normed   = (const float*)d_in[0];
    const float* unnormed = (const float*)d_in[1];
    const float* pts      = (const float*)d_in[2];
    float* out = (float*)d_out;

    k_scan<<<NB, 256>>>(normed, unnormed, pts);
    dim3 g(NCH, NB);
    k_wd<<<g, 256>>>(pts, out);
}